// round 1
// baseline (speedup 1.0000x reference)
#include <cuda_runtime.h>
#include <cuda_bf16.h>
#include <math.h>

// ---------------------------------------------------------------------------
// TransformerLayer: B=8, S=512, D=1024, H=16, HD=64, FF=4096, eps=1e-5
// fp32 baseline. 8 kernel launches, all graph-capturable, no allocations.
// ---------------------------------------------------------------------------

#define Bc 8
#define Sc 512
#define Dc 1024
#define Hc 16
#define HDc 64
#define FFc 4096
#define ROWS (Bc*Sc)          // 4096

// Scratch (static device memory; allowed per harness rules)
__device__ float g_h   [ROWS*Dc];
__device__ float g_q   [ROWS*Dc];
__device__ float g_k   [ROWS*Dc];
__device__ float g_v   [ROWS*Dc];
__device__ float g_ctx [ROWS*Dc];
__device__ float g_cache[ROWS*Dc];
__device__ float g_h2  [ROWS*Dc];
__device__ float g_ff  [ROWS*FFc];

// ---------------------------------------------------------------------------
// LayerNorm: one block per row, 256 threads, 4 elems/thread (float4)
// ---------------------------------------------------------------------------
__global__ __launch_bounds__(256) void layernorm_kernel(
    const float* __restrict__ x, const float* __restrict__ gamma,
    const float* __restrict__ beta, float* __restrict__ out)
{
    __shared__ float red[16];
    int row = blockIdx.x;
    const float4* xr = (const float4*)(x + (size_t)row * Dc);
    float4 v = xr[threadIdx.x];
    float s  = v.x + v.y + v.z + v.w;
    float sq = v.x*v.x + v.y*v.y + v.z*v.z + v.w*v.w;
    #pragma unroll
    for (int off = 16; off; off >>= 1) {
        s  += __shfl_xor_sync(0xffffffffu, s,  off);
        sq += __shfl_xor_sync(0xffffffffu, sq, off);
    }
    int warp = threadIdx.x >> 5, lane = threadIdx.x & 31;
    if (lane == 0) { red[warp] = s; red[8 + warp] = sq; }
    __syncthreads();
    float ts = 0.f, tsq = 0.f;
    #pragma unroll
    for (int i = 0; i < 8; i++) { ts += red[i]; tsq += red[8 + i]; }
    float mean = ts * (1.0f / Dc);
    float var  = tsq * (1.0f / Dc) - mean * mean;
    float inv  = rsqrtf(var + 1e-5f);
    float4 g4 = ((const float4*)gamma)[threadIdx.x];
    float4 b4 = ((const float4*)beta )[threadIdx.x];
    float4 o;
    o.x = (v.x - mean) * inv * g4.x + b4.x;
    o.y = (v.y - mean) * inv * g4.y + b4.y;
    o.z = (v.z - mean) * inv * g4.z + b4.z;
    o.w = (v.w - mean) * inv * g4.w + b4.w;
    ((float4*)(out + (size_t)row * Dc))[threadIdx.x] = o;
}

// ---------------------------------------------------------------------------
// SGEMM 128x128x8, 256 threads, 8x8/thread.
//  BMODE 0: B row-major [K,N]
//  BMODE 1: B head-blocked: B[k][n] = Bp[(n>>6)*K*64 + k*64 + (n&63)]  (Wq/Wk/Wv)
//  EPI 0: C = acc
//  EPI 1: C = acc + bias[n] + resid[m*N+n]
//  EPI 2: C = gelu_exact(acc + bias[n])
// ---------------------------------------------------------------------------
template<int BMODE, int EPI>
__global__ __launch_bounds__(256) void gemm128(
    const float* __restrict__ A, const float* __restrict__ B, float* __restrict__ C,
    int M, int N, int K,
    const float* __restrict__ bias, const float* __restrict__ resid)
{
    __shared__ float As[8][128];
    __shared__ float Bs[8][128];
    int m0 = blockIdx.y * 128, n0 = blockIdx.x * 128;
    int t = threadIdx.x;
    int tx = t & 15, ty = t >> 4;

    float acc[8][8];
    #pragma unroll
    for (int i = 0; i < 8; i++)
        #pragma unroll
        for (int j = 0; j < 8; j++) acc[i][j] = 0.f;

    int arow = t >> 1, ak = (t & 1) * 4;   // A: float4 per thread
    int bk = t >> 5,  bn = (t & 31) * 4;   // B: float4 per thread

    for (int k0 = 0; k0 < K; k0 += 8) {
        float4 av = *(const float4*)(A + (size_t)(m0 + arow) * K + k0 + ak);
        float4 bv;
        if (BMODE == 0) {
            bv = *(const float4*)(B + (size_t)(k0 + bk) * N + n0 + bn);
        } else {
            int n = n0 + bn;
            bv = *(const float4*)(B + (size_t)(n >> 6) * K * 64 + (size_t)(k0 + bk) * 64 + (n & 63));
        }
        As[ak + 0][arow] = av.x; As[ak + 1][arow] = av.y;
        As[ak + 2][arow] = av.z; As[ak + 3][arow] = av.w;
        *(float4*)&Bs[bk][bn] = bv;
        __syncthreads();

        #pragma unroll
        for (int kk = 0; kk < 8; kk++) {
            float a[8], b[8];
            #pragma unroll
            for (int i = 0; i < 8; i++) a[i] = As[kk][ty * 8 + i];
            #pragma unroll
            for (int j = 0; j < 8; j++) b[j] = Bs[kk][tx * 8 + j];
            #pragma unroll
            for (int i = 0; i < 8; i++)
                #pragma unroll
                for (int j = 0; j < 8; j++) acc[i][j] += a[i] * b[j];
        }
        __syncthreads();
    }

    #pragma unroll
    for (int i = 0; i < 8; i++) {
        int m = m0 + ty * 8 + i;
        #pragma unroll
        for (int j = 0; j < 8; j++) {
            int n = n0 + tx * 8 + j;
            float v = acc[i][j];
            if (EPI == 1) v += bias[n] + resid[(size_t)m * N + n];
            if (EPI == 2) {
                v += bias[n];
                v = 0.5f * v * (1.0f + erff(v * 0.70710678118654752f));
            }
            C[(size_t)m * N + n] = v;
        }
    }
}

// ---------------------------------------------------------------------------
// Causal attention, fp32, online softmax. One block per (qtile, head, batch).
// Q/K/V/O layout: [B, S, H*HD] (i.e., elem at ((b*S+s)*D + h*64 + e)).
// smem: sQ^T[64e][68], sK^T[64e][68], sV[64k][68], sP[64q][65]
// ---------------------------------------------------------------------------
#define QP 68
#define PP 65
#define ATTN_SMEM ((3*64*QP + 64*PP) * 4)

__global__ __launch_bounds__(256) void attn_kernel(
    const float* __restrict__ Qg, const float* __restrict__ Kg,
    const float* __restrict__ Vg, float* __restrict__ Og)
{
    extern __shared__ float sm[];
    float* sQ = sm;                    // transposed: [e][row], stride QP
    float* sK = sm + 64 * QP;          // transposed: [e][col], stride QP
    float* sV = sm + 2 * 64 * QP;      // [k][col], stride QP
    float* sP = sm + 3 * 64 * QP;      // [qrow][k], stride PP

    int qt = blockIdx.x;   // 0..7
    int h  = blockIdx.y;   // 0..15
    int b  = blockIdx.z;   // 0..7
    int t  = threadIdx.x;
    int tx = t & 15, ty = t >> 4;

    size_t base = ((size_t)b * Sc) * Dc + h * HDc;

    // Load Q tile (transposed into smem)
    #pragma unroll
    for (int i = 0; i < 4; i++) {
        int fi = t + i * 256;                  // 0..1023
        int r = fi >> 4, e4 = (fi & 15) * 4;
        float4 v = *(const float4*)(Qg + base + (size_t)(qt * 64 + r) * Dc + e4);
        sQ[(e4 + 0) * QP + r] = v.x;
        sQ[(e4 + 1) * QP + r] = v.y;
        sQ[(e4 + 2) * QP + r] = v.z;
        sQ[(e4 + 3) * QP + r] = v.w;
    }

    float mrow[4], lrow[4], acc[4][4];
    #pragma unroll
    for (int i = 0; i < 4; i++) {
        mrow[i] = -INFINITY; lrow[i] = 0.f;
        #pragma unroll
        for (int j = 0; j < 4; j++) acc[i][j] = 0.f;
    }

    for (int kt = 0; kt <= qt; kt++) {
        // Load K (transposed) and V tiles
        #pragma unroll
        for (int i = 0; i < 4; i++) {
            int fi = t + i * 256;
            int r = fi >> 4, e4 = (fi & 15) * 4;
            float4 kv = *(const float4*)(Kg + base + (size_t)(kt * 64 + r) * Dc + e4);
            sK[(e4 + 0) * QP + r] = kv.x;
            sK[(e4 + 1) * QP + r] = kv.y;
            sK[(e4 + 2) * QP + r] = kv.z;
            sK[(e4 + 3) * QP + r] = kv.w;
            float4 vv = *(const float4*)(Vg + base + (size_t)(kt * 64 + r) * Dc + e4);
            *(float4*)&sV[r * QP + e4] = vv;
        }
        __syncthreads();   // K,V (and Q on first iter) visible

        // S = Q @ K^T  (4x4 per thread)
        float s[4][4];
        #pragma unroll
        for (int i = 0; i < 4; i++)
            #pragma unroll
            for (int j = 0; j < 4; j++) s[i][j] = 0.f;
        #pragma unroll 4
        for (int e = 0; e < 64; e++) {
            float4 qa = *(const float4*)&sQ[e * QP + ty * 4];
            float4 kb = *(const float4*)&sK[e * QP + tx * 4];
            s[0][0] += qa.x * kb.x; s[0][1] += qa.x * kb.y; s[0][2] += qa.x * kb.z; s[0][3] += qa.x * kb.w;
            s[1][0] += qa.y * kb.x; s[1][1] += qa.y * kb.y; s[1][2] += qa.y * kb.z; s[1][3] += qa.y * kb.w;
            s[2][0] += qa.z * kb.x; s[2][1] += qa.z * kb.y; s[2][2] += qa.z * kb.z; s[2][3] += qa.z * kb.w;
            s[3][0] += qa.w * kb.x; s[3][1] += qa.w * kb.y; s[3][2] += qa.w * kb.z; s[3][3] += qa.w * kb.w;
        }

        bool diag = (kt == qt);
        #pragma unroll
        for (int i = 0; i < 4; i++)
            #pragma unroll
            for (int j = 0; j < 4; j++) {
                s[i][j] *= 0.125f;                       // 1/sqrt(64)
                if (diag && (tx * 4 + j) > (ty * 4 + i)) s[i][j] = -1e10f;
            }

        // Online softmax update
        float p[4][4], rs[4];
        #pragma unroll
        for (int i = 0; i < 4; i++) {
            float mt = fmaxf(fmaxf(s[i][0], s[i][1]), fmaxf(s[i][2], s[i][3]));
            #pragma unroll
            for (int off = 8; off; off >>= 1)
                mt = fmaxf(mt, __shfl_xor_sync(0xffffffffu, mt, off, 16));
            float mn = fmaxf(mrow[i], mt);
            float corr = __expf(mrow[i] - mn);
            float r = 0.f;
            #pragma unroll
            for (int j = 0; j < 4; j++) { p[i][j] = __expf(s[i][j] - mn); r += p[i][j]; }
            #pragma unroll
            for (int off = 8; off; off >>= 1)
                r += __shfl_xor_sync(0xffffffffu, r, off, 16);
            rs[i] = r;
            lrow[i] = lrow[i] * corr + r;
            mrow[i] = mn;
            #pragma unroll
            for (int j = 0; j < 4; j++) acc[i][j] *= corr;
        }
        (void)rs;

        __syncthreads();   // all threads done reading sK before reusing... (sP separate, this orders prior-tile sP reads too)
        #pragma unroll
        for (int i = 0; i < 4; i++)
            #pragma unroll
            for (int j = 0; j < 4; j++)
                sP[(ty * 4 + i) * PP + tx * 4 + j] = p[i][j];
        __syncthreads();   // P visible

        // acc += P @ V
        #pragma unroll 4
        for (int k = 0; k < 64; k++) {
            float4 vb = *(const float4*)&sV[k * QP + tx * 4];
            float p0 = sP[(ty * 4 + 0) * PP + k];
            float p1 = sP[(ty * 4 + 1) * PP + k];
            float p2 = sP[(ty * 4 + 2) * PP + k];
            float p3 = sP[(ty * 4 + 3) * PP + k];
            acc[0][0] += p0 * vb.x; acc[0][1] += p0 * vb.y; acc[0][2] += p0 * vb.z; acc[0][3] += p0 * vb.w;
            acc[1][0] += p1 * vb.x; acc[1][1] += p1 * vb.y; acc[1][2] += p1 * vb.z; acc[1][3] += p1 * vb.w;
            acc[2][0] += p2 * vb.x; acc[2][1] += p2 * vb.y; acc[2][2] += p2 * vb.z; acc[2][3] += p2 * vb.w;
            acc[3][0] += p3 * vb.x; acc[3][1] += p3 * vb.y; acc[3][2] += p3 * vb.z; acc[3][3] += p3 * vb.w;
        }
        __syncthreads();   // done with sV/sP before next tile's loads
    }

    // Write O = acc / l
    #pragma unroll
    for (int i = 0; i < 4; i++) {
        float inv = 1.0f / lrow[i];
        float4 o;
        o.x = acc[i][0] * inv; o.y = acc[i][1] * inv;
        o.z = acc[i][2] * inv; o.w = acc[i][3] * inv;
        *(float4*)(Og + base + (size_t)(qt * 64 + ty * 4 + i) * Dc + tx * 4) = o;
    }
}

// ---------------------------------------------------------------------------
extern "C" void kernel_launch(void* const* d_in, const int* in_sizes, int n_in,
                              void* d_out, int out_size)
{
    const float* x   = (const float*)d_in[0];
    const float* Wq  = (const float*)d_in[1];
    const float* Wk  = (const float*)d_in[2];
    const float* Wv  = (const float*)d_in[3];
    const float* Wo  = (const float*)d_in[4];
    const float* bo  = (const float*)d_in[5];
    const float* g1  = (const float*)d_in[6];
    const float* b1  = (const float*)d_in[7];
    const float* g2  = (const float*)d_in[8];
    const float* b2  = (const float*)d_in[9];
    const float* W1  = (const float*)d_in[10];
    const float* bf1 = (const float*)d_in[11];
    const float* W2  = (const float*)d_in[12];
    const float* bf2 = (const float*)d_in[13];
    float* out = (float*)d_out;

    float *h, *q, *k, *v, *ctx, *cache, *h2, *ff;
    cudaGetSymbolAddress((void**)&h,     g_h);
    cudaGetSymbolAddress((void**)&q,     g_q);
    cudaGetSymbolAddress((void**)&k,     g_k);
    cudaGetSymbolAddress((void**)&v,     g_v);
    cudaGetSymbolAddress((void**)&ctx,   g_ctx);
    cudaGetSymbolAddress((void**)&cache, g_cache);
    cudaGetSymbolAddress((void**)&h2,    g_h2);
    cudaGetSymbolAddress((void**)&ff,    g_ff);

    // 1. LN1
    layernorm_kernel<<<ROWS, 256>>>(x, g1, b1, h);

    // 2. Q/K/V projections (B head-blocked), outputs already in [B,S,H,E]
    dim3 gqkv(Dc / 128, ROWS / 128);   // (8, 32)
    gemm128<1, 0><<<gqkv, 256>>>(h, Wq, q, ROWS, Dc, Dc, nullptr, nullptr);
    gemm128<1, 0><<<gqkv, 256>>>(h, Wk, k, ROWS, Dc, Dc, nullptr, nullptr);
    gemm128<1, 0><<<gqkv, 256>>>(h, Wv, v, ROWS, Dc, Dc, nullptr, nullptr);

    // 3. Causal attention
    cudaFuncSetAttribute(attn_kernel, cudaFuncAttributeMaxDynamicSharedMemorySize, ATTN_SMEM);
    attn_kernel<<<dim3(Sc / 64, Hc, Bc), 256, ATTN_SMEM>>>(q, k, v, ctx);

    // 4. Output projection + bias + residual(x) -> cache
    gemm128<0, 1><<<gqkv, 256>>>(ctx, Wo, cache, ROWS, Dc, Dc, bo, x);

    // 5. LN2
    layernorm_kernel<<<ROWS, 256>>>(cache, g2, b2, h2);

    // 6. FF1 + bias + exact GELU
    dim3 gff1(FFc / 128, ROWS / 128);  // (32, 32)
    gemm128<0, 2><<<gff1, 256>>>(h2, W1, ff, ROWS, FFc, Dc, bf1, nullptr);

    // 7. FF2 + bias + residual(cache) -> out
    gemm128<0, 1><<<gqkv, 256>>>(ff, W2, out, ROWS, Dc, FFc, bf2, cache);
}

// round 2
// speedup vs baseline: 2.8351x; 2.8351x over previous
#include <cuda_runtime.h>
#include <cuda_bf16.h>
#include <math.h>
#include <stdint.h>

// ---------------------------------------------------------------------------
// TransformerLayer: B=8, S=512, D=1024, H=16, HD=64, FF=4096, eps=1e-5
// GEMMs on tf32 mma.sync tensor path; attention + LN fp32.
// ---------------------------------------------------------------------------

#define Bc 8
#define Sc 512
#define Dc 1024
#define Hc 16
#define HDc 64
#define FFc 4096
#define ROWS (Bc*Sc)          // 4096

__device__ float g_h   [ROWS*Dc];
__device__ float g_q   [ROWS*Dc];
__device__ float g_k   [ROWS*Dc];
__device__ float g_v   [ROWS*Dc];
__device__ float g_ctx [ROWS*Dc];
__device__ float g_cache[ROWS*Dc];
__device__ float g_h2  [ROWS*Dc];
__device__ float g_ff  [ROWS*FFc];

// ---------------------------------------------------------------------------
// LayerNorm
// ---------------------------------------------------------------------------
__global__ __launch_bounds__(256) void layernorm_kernel(
    const float* __restrict__ x, const float* __restrict__ gamma,
    const float* __restrict__ beta, float* __restrict__ out)
{
    __shared__ float red[16];
    int row = blockIdx.x;
    const float4* xr = (const float4*)(x + (size_t)row * Dc);
    float4 v = xr[threadIdx.x];
    float s  = v.x + v.y + v.z + v.w;
    float sq = v.x*v.x + v.y*v.y + v.z*v.z + v.w*v.w;
    #pragma unroll
    for (int off = 16; off; off >>= 1) {
        s  += __shfl_xor_sync(0xffffffffu, s,  off);
        sq += __shfl_xor_sync(0xffffffffu, sq, off);
    }
    int warp = threadIdx.x >> 5, lane = threadIdx.x & 31;
    if (lane == 0) { red[warp] = s; red[8 + warp] = sq; }
    __syncthreads();
    float ts = 0.f, tsq = 0.f;
    #pragma unroll
    for (int i = 0; i < 8; i++) { ts += red[i]; tsq += red[8 + i]; }
    float mean = ts * (1.0f / Dc);
    float var  = tsq * (1.0f / Dc) - mean * mean;
    float inv  = rsqrtf(var + 1e-5f);
    float4 g4 = ((const float4*)gamma)[threadIdx.x];
    float4 b4 = ((const float4*)beta )[threadIdx.x];
    float4 o;
    o.x = (v.x - mean) * inv * g4.x + b4.x;
    o.y = (v.y - mean) * inv * g4.y + b4.y;
    o.z = (v.z - mean) * inv * g4.z + b4.z;
    o.w = (v.w - mean) * inv * g4.w + b4.w;
    ((float4*)(out + (size_t)row * Dc))[threadIdx.x] = o;
}

// ---------------------------------------------------------------------------
// tf32 helpers
// ---------------------------------------------------------------------------
__device__ __forceinline__ uint32_t f2tf32(float f) {
    uint32_t u;
    asm("cvt.rna.tf32.f32 %0, %1;" : "=r"(u) : "f"(f));
    return u;
}

__device__ __forceinline__ void mma_tf32(float (&d)[4],
                                         const uint32_t (&a)[4],
                                         const uint32_t (&b)[2]) {
    asm volatile(
        "mma.sync.aligned.m16n8k8.row.col.f32.tf32.tf32.f32 "
        "{%0,%1,%2,%3}, {%4,%5,%6,%7}, {%8,%9}, {%0,%1,%2,%3};\n"
        : "+f"(d[0]), "+f"(d[1]), "+f"(d[2]), "+f"(d[3])
        : "r"(a[0]), "r"(a[1]), "r"(a[2]), "r"(a[3]), "r"(b[0]), "r"(b[1]));
}

// ---------------------------------------------------------------------------
// tf32 GEMM: 128x128 block, BK=16, 256 threads = 8 warps (4 M x 2 N),
// warptile 32x64, mma m16n8k8 (2 M-frags x 8 N-frags x 2 K-steps).
//  BMODE 0: B row-major [K,N]
//  BMODE 1: B head-blocked: B[k][n] = Bp[(n>>6)*K*64 + k*64 + (n&63)]
//  EPI 0: C = acc   1: acc+bias+resid   2: gelu(acc+bias)
// ---------------------------------------------------------------------------
#define ASTR 20     // As stride (BK=16 + 4) -> A-frag LDS conflict-free
#define BSTR 136    // Bs stride (128 + 8)   -> B-frag LDS conflict-free

template<int BMODE, int EPI>
__global__ __launch_bounds__(256) void gemm_tf32(
    const float* __restrict__ A, const float* __restrict__ B, float* __restrict__ C,
    int M, int N, int K,
    const float* __restrict__ bias, const float* __restrict__ resid)
{
    __shared__ uint32_t As[128 * ASTR];   // [m][k] row-major, stride 20
    __shared__ uint32_t Bs[16 * BSTR];    // [k][n] row-major, stride 136

    int m0 = blockIdx.y * 128, n0 = blockIdx.x * 128;
    int t = threadIdx.x;
    int w = t >> 5, lane = t & 31;
    int wm = w >> 1, wn = w & 1;          // warp grid 4x2
    int gid = lane >> 2, tid = lane & 3;  // mma fragment coords

    float acc[2][8][4];
    #pragma unroll
    for (int mf = 0; mf < 2; mf++)
        #pragma unroll
        for (int nf = 0; nf < 8; nf++)
            #pragma unroll
            for (int c = 0; c < 4; c++) acc[mf][nf][c] = 0.f;

    // Global load assignments (per thread: 2 float4 of A, 2 float4 of B)
    int af0 = t, af1 = t + 256;           // A float4 index: row = f>>2, kq = (f&3)*4
    int bf0 = t, bf1 = t + 256;           // B float4 index: k = f>>5, nq = (f&31)*4

    float4 pa0, pa1, pb0, pb1;

    auto loadA = [&](int f, int k0) -> float4 {
        int row = f >> 2, kq = (f & 3) * 4;
        return *(const float4*)(A + (size_t)(m0 + row) * K + k0 + kq);
    };
    auto loadB = [&](int f, int k0) -> float4 {
        int k = f >> 5, nq = (f & 31) * 4;
        if (BMODE == 0)
            return *(const float4*)(B + (size_t)(k0 + k) * N + n0 + nq);
        int n = n0 + nq;
        return *(const float4*)(B + (size_t)(n >> 6) * K * 64 + (size_t)(k0 + k) * 64 + (n & 63));
    };
    auto stash = [&]() {
        {   int row = af0 >> 2, kq = (af0 & 3) * 4;
            uint32_t* p = &As[row * ASTR + kq];
            p[0] = f2tf32(pa0.x); p[1] = f2tf32(pa0.y); p[2] = f2tf32(pa0.z); p[3] = f2tf32(pa0.w); }
        {   int row = af1 >> 2, kq = (af1 & 3) * 4;
            uint32_t* p = &As[row * ASTR + kq];
            p[0] = f2tf32(pa1.x); p[1] = f2tf32(pa1.y); p[2] = f2tf32(pa1.z); p[3] = f2tf32(pa1.w); }
        {   int k = bf0 >> 5, nq = (bf0 & 31) * 4;
            uint4 u; u.x = f2tf32(pb0.x); u.y = f2tf32(pb0.y); u.z = f2tf32(pb0.z); u.w = f2tf32(pb0.w);
            *(uint4*)&Bs[k * BSTR + nq] = u; }
        {   int k = bf1 >> 5, nq = (bf1 & 31) * 4;
            uint4 u; u.x = f2tf32(pb1.x); u.y = f2tf32(pb1.y); u.z = f2tf32(pb1.z); u.w = f2tf32(pb1.w);
            *(uint4*)&Bs[k * BSTR + nq] = u; }
    };
    auto compute = [&]() {
        #pragma unroll
        for (int ks = 0; ks < 2; ks++) {
            int kk = ks * 8;
            uint32_t afr[2][4], bfr[8][2];
            #pragma unroll
            for (int mf = 0; mf < 2; mf++) {
                int mb = wm * 32 + mf * 16 + gid;
                afr[mf][0] = As[(mb    ) * ASTR + kk + tid];
                afr[mf][1] = As[(mb + 8) * ASTR + kk + tid];
                afr[mf][2] = As[(mb    ) * ASTR + kk + tid + 4];
                afr[mf][3] = As[(mb + 8) * ASTR + kk + tid + 4];
            }
            #pragma unroll
            for (int nf = 0; nf < 8; nf++) {
                int nb = wn * 64 + nf * 8 + gid;
                bfr[nf][0] = Bs[(kk + tid    ) * BSTR + nb];
                bfr[nf][1] = Bs[(kk + tid + 4) * BSTR + nb];
            }
            #pragma unroll
            for (int mf = 0; mf < 2; mf++)
                #pragma unroll
                for (int nf = 0; nf < 8; nf++)
                    mma_tf32(acc[mf][nf], afr[mf], bfr[nf]);
        }
    };

    // Prologue: load tile 0
    pa0 = loadA(af0, 0); pa1 = loadA(af1, 0);
    pb0 = loadB(bf0, 0); pb1 = loadB(bf1, 0);
    stash();
    __syncthreads();

    for (int k0 = 16; k0 < K; k0 += 16) {
        // prefetch next tile from global while computing current
        pa0 = loadA(af0, k0); pa1 = loadA(af1, k0);
        pb0 = loadB(bf0, k0); pb1 = loadB(bf1, k0);
        compute();
        __syncthreads();
        stash();
        __syncthreads();
    }
    compute();

    // Epilogue
    #pragma unroll
    for (int mf = 0; mf < 2; mf++) {
        int r0 = m0 + wm * 32 + mf * 16 + gid;
        #pragma unroll
        for (int nf = 0; nf < 8; nf++) {
            int c0 = n0 + wn * 64 + nf * 8 + 2 * tid;
            float v0 = acc[mf][nf][0], v1 = acc[mf][nf][1];   // row r0
            float v2 = acc[mf][nf][2], v3 = acc[mf][nf][3];   // row r0+8
            if (EPI == 1) {
                float b0v = bias[c0], b1v = bias[c0 + 1];
                v0 += b0v + resid[(size_t)r0 * N + c0];
                v1 += b1v + resid[(size_t)r0 * N + c0 + 1];
                v2 += b0v + resid[(size_t)(r0 + 8) * N + c0];
                v3 += b1v + resid[(size_t)(r0 + 8) * N + c0 + 1];
            }
            if (EPI == 2) {
                float b0v = bias[c0], b1v = bias[c0 + 1];
                v0 += b0v; v1 += b1v; v2 += b0v; v3 += b1v;
                v0 = 0.5f * v0 * (1.0f + erff(v0 * 0.70710678118654752f));
                v1 = 0.5f * v1 * (1.0f + erff(v1 * 0.70710678118654752f));
                v2 = 0.5f * v2 * (1.0f + erff(v2 * 0.70710678118654752f));
                v3 = 0.5f * v3 * (1.0f + erff(v3 * 0.70710678118654752f));
            }
            *(float2*)(C + (size_t)r0 * N + c0)       = make_float2(v0, v1);
            *(float2*)(C + (size_t)(r0 + 8) * N + c0) = make_float2(v2, v3);
        }
    }
}

// ---------------------------------------------------------------------------
// Causal attention (fp32, online softmax), unchanged from round 1.
// ---------------------------------------------------------------------------
#define QP 68
#define PP 65
#define ATTN_SMEM ((3*64*QP + 64*PP) * 4)

__global__ __launch_bounds__(256) void attn_kernel(
    const float* __restrict__ Qg, const float* __restrict__ Kg,
    const float* __restrict__ Vg, float* __restrict__ Og)
{
    extern __shared__ float sm[];
    float* sQ = sm;
    float* sK = sm + 64 * QP;
    float* sV = sm + 2 * 64 * QP;
    float* sP = sm + 3 * 64 * QP;

    int qt = blockIdx.x, h = blockIdx.y, b = blockIdx.z;
    int t = threadIdx.x;
    int tx = t & 15, ty = t >> 4;

    size_t base = ((size_t)b * Sc) * Dc + h * HDc;

    #pragma unroll
    for (int i = 0; i < 4; i++) {
        int fi = t + i * 256;
        int r = fi >> 4, e4 = (fi & 15) * 4;
        float4 v = *(const float4*)(Qg + base + (size_t)(qt * 64 + r) * Dc + e4);
        sQ[(e4 + 0) * QP + r] = v.x;
        sQ[(e4 + 1) * QP + r] = v.y;
        sQ[(e4 + 2) * QP + r] = v.z;
        sQ[(e4 + 3) * QP + r] = v.w;
    }

    float mrow[4], lrow[4], acc[4][4];
    #pragma unroll
    for (int i = 0; i < 4; i++) {
        mrow[i] = -INFINITY; lrow[i] = 0.f;
        #pragma unroll
        for (int j = 0; j < 4; j++) acc[i][j] = 0.f;
    }

    for (int kt = 0; kt <= qt; kt++) {
        #pragma unroll
        for (int i = 0; i < 4; i++) {
            int fi = t + i * 256;
            int r = fi >> 4, e4 = (fi & 15) * 4;
            float4 kv = *(const float4*)(Kg + base + (size_t)(kt * 64 + r) * Dc + e4);
            sK[(e4 + 0) * QP + r] = kv.x;
            sK[(e4 + 1) * QP + r] = kv.y;
            sK[(e4 + 2) * QP + r] = kv.z;
            sK[(e4 + 3) * QP + r] = kv.w;
            float4 vv = *(const float4*)(Vg + base + (size_t)(kt * 64 + r) * Dc + e4);
            *(float4*)&sV[r * QP + e4] = vv;
        }
        __syncthreads();

        float s[4][4];
        #pragma unroll
        for (int i = 0; i < 4; i++)
            #pragma unroll
            for (int j = 0; j < 4; j++) s[i][j] = 0.f;
        #pragma unroll 4
        for (int e = 0; e < 64; e++) {
            float4 qa = *(const float4*)&sQ[e * QP + ty * 4];
            float4 kb = *(const float4*)&sK[e * QP + tx * 4];
            s[0][0] += qa.x * kb.x; s[0][1] += qa.x * kb.y; s[0][2] += qa.x * kb.z; s[0][3] += qa.x * kb.w;
            s[1][0] += qa.y * kb.x; s[1][1] += qa.y * kb.y; s[1][2] += qa.y * kb.z; s[1][3] += qa.y * kb.w;
            s[2][0] += qa.z * kb.x; s[2][1] += qa.z * kb.y; s[2][2] += qa.z * kb.z; s[2][3] += qa.z * kb.w;
            s[3][0] += qa.w * kb.x; s[3][1] += qa.w * kb.y; s[3][2] += qa.w * kb.z; s[3][3] += qa.w * kb.w;
        }

        bool diag = (kt == qt);
        #pragma unroll
        for (int i = 0; i < 4; i++)
            #pragma unroll
            for (int j = 0; j < 4; j++) {
                s[i][j] *= 0.125f;
                if (diag && (tx * 4 + j) > (ty * 4 + i)) s[i][j] = -1e10f;
            }

        float p[4][4];
        #pragma unroll
        for (int i = 0; i < 4; i++) {
            float mt = fmaxf(fmaxf(s[i][0], s[i][1]), fmaxf(s[i][2], s[i][3]));
            #pragma unroll
            for (int off = 8; off; off >>= 1)
                mt = fmaxf(mt, __shfl_xor_sync(0xffffffffu, mt, off, 16));
            float mn = fmaxf(mrow[i], mt);
            float corr = __expf(mrow[i] - mn);
            float r = 0.f;
            #pragma unroll
            for (int j = 0; j < 4; j++) { p[i][j] = __expf(s[i][j] - mn); r += p[i][j]; }
            #pragma unroll
            for (int off = 8; off; off >>= 1)
                r += __shfl_xor_sync(0xffffffffu, r, off, 16);
            lrow[i] = lrow[i] * corr + r;
            mrow[i] = mn;
            #pragma unroll
            for (int j = 0; j < 4; j++) acc[i][j] *= corr;
        }

        __syncthreads();
        #pragma unroll
        for (int i = 0; i < 4; i++)
            #pragma unroll
            for (int j = 0; j < 4; j++)
                sP[(ty * 4 + i) * PP + tx * 4 + j] = p[i][j];
        __syncthreads();

        #pragma unroll 4
        for (int k = 0; k < 64; k++) {
            float4 vb = *(const float4*)&sV[k * QP + tx * 4];
            float p0 = sP[(ty * 4 + 0) * PP + k];
            float p1 = sP[(ty * 4 + 1) * PP + k];
            float p2 = sP[(ty * 4 + 2) * PP + k];
            float p3 = sP[(ty * 4 + 3) * PP + k];
            acc[0][0] += p0 * vb.x; acc[0][1] += p0 * vb.y; acc[0][2] += p0 * vb.z; acc[0][3] += p0 * vb.w;
            acc[1][0] += p1 * vb.x; acc[1][1] += p1 * vb.y; acc[1][2] += p1 * vb.z; acc[1][3] += p1 * vb.w;
            acc[2][0] += p2 * vb.x; acc[2][1] += p2 * vb.y; acc[2][2] += p2 * vb.z; acc[2][3] += p2 * vb.w;
            acc[3][0] += p3 * vb.x; acc[3][1] += p3 * vb.y; acc[3][2] += p3 * vb.z; acc[3][3] += p3 * vb.w;
        }
        __syncthreads();
    }

    #pragma unroll
    for (int i = 0; i < 4; i++) {
        float inv = 1.0f / lrow[i];
        float4 o;
        o.x = acc[i][0] * inv; o.y = acc[i][1] * inv;
        o.z = acc[i][2] * inv; o.w = acc[i][3] * inv;
        *(float4*)(Og + base + (size_t)(qt * 64 + ty * 4 + i) * Dc + tx * 4) = o;
    }
}

// ---------------------------------------------------------------------------
extern "C" void kernel_launch(void* const* d_in, const int* in_sizes, int n_in,
                              void* d_out, int out_size)
{
    const float* x   = (const float*)d_in[0];
    const float* Wq  = (const float*)d_in[1];
    const float* Wk  = (const float*)d_in[2];
    const float* Wv  = (const float*)d_in[3];
    const float* Wo  = (const float*)d_in[4];
    const float* bo  = (const float*)d_in[5];
    const float* g1  = (const float*)d_in[6];
    const float* b1  = (const float*)d_in[7];
    const float* g2  = (const float*)d_in[8];
    const float* b2  = (const float*)d_in[9];
    const float* W1  = (const float*)d_in[10];
    const float* bf1 = (const float*)d_in[11];
    const float* W2  = (const float*)d_in[12];
    const float* bf2 = (const float*)d_in[13];
    float* out = (float*)d_out;

    float *h, *q, *k, *v, *ctx, *cache, *h2, *ff;
    cudaGetSymbolAddress((void**)&h,     g_h);
    cudaGetSymbolAddress((void**)&q,     g_q);
    cudaGetSymbolAddress((void**)&k,     g_k);
    cudaGetSymbolAddress((void**)&v,     g_v);
    cudaGetSymbolAddress((void**)&ctx,   g_ctx);
    cudaGetSymbolAddress((void**)&cache, g_cache);
    cudaGetSymbolAddress((void**)&h2,    g_h2);
    cudaGetSymbolAddress((void**)&ff,    g_ff);

    // 1. LN1
    layernorm_kernel<<<ROWS, 256>>>(x, g1, b1, h);

    // 2. Q/K/V projections (tf32 tensor cores, head-blocked B)
    dim3 gqkv(Dc / 128, ROWS / 128);   // (8, 32)
    gemm_tf32<1, 0><<<gqkv, 256>>>(h, Wq, q, ROWS, Dc, Dc, nullptr, nullptr);
    gemm_tf32<1, 0><<<gqkv, 256>>>(h, Wk, k, ROWS, Dc, Dc, nullptr, nullptr);
    gemm_tf32<1, 0><<<gqkv, 256>>>(h, Wv, v, ROWS, Dc, Dc, nullptr, nullptr);

    // 3. Causal attention (fp32)
    cudaFuncSetAttribute(attn_kernel, cudaFuncAttributeMaxDynamicSharedMemorySize, ATTN_SMEM);
    attn_kernel<<<dim3(Sc / 64, Hc, Bc), 256, ATTN_SMEM>>>(q, k, v, ctx);

    // 4. Output projection + bias + residual(x) -> cache
    gemm_tf32<0, 1><<<gqkv, 256>>>(ctx, Wo, cache, ROWS, Dc, Dc, bo, x);

    // 5. LN2
    layernorm_kernel<<<ROWS, 256>>>(cache, g2, b2, h2);

    // 6. FF1 + bias + exact GELU
    dim3 gff1(FFc / 128, ROWS / 128);  // (32, 32)
    gemm_tf32<0, 2><<<gff1, 256>>>(h2, W1, ff, ROWS, FFc, Dc, bf1, nullptr);

    // 7. FF2 + bias + residual(cache) -> out
    gemm_tf32<0, 1><<<gqkv, 256>>>(ff, W2, out, ROWS, Dc, FFc, bf2, cache);
}

// round 3
// speedup vs baseline: 3.2405x; 1.1430x over previous
#include <cuda_runtime.h>
#include <cuda_bf16.h>
#include <math.h>
#include <stdint.h>

// ---------------------------------------------------------------------------
// TransformerLayer: B=8, S=512, D=1024, H=16, HD=64, FF=4096, eps=1e-5
// All GEMMs + attention on tf32 mma.sync; LN fp32.
// ---------------------------------------------------------------------------

#define Bc 8
#define Sc 512
#define Dc 1024
#define Hc 16
#define HDc 64
#define FFc 4096
#define ROWS (Bc*Sc)          // 4096

__device__ float g_h   [ROWS*Dc];
__device__ float g_q   [ROWS*Dc];
__device__ float g_k   [ROWS*Dc];
__device__ float g_v   [ROWS*Dc];
__device__ float g_ctx [ROWS*Dc];
__device__ float g_cache[ROWS*Dc];
__device__ float g_h2  [ROWS*Dc];
__device__ float g_ff  [ROWS*FFc];

// ---------------------------------------------------------------------------
// LayerNorm
// ---------------------------------------------------------------------------
__global__ __launch_bounds__(256) void layernorm_kernel(
    const float* __restrict__ x, const float* __restrict__ gamma,
    const float* __restrict__ beta, float* __restrict__ out)
{
    __shared__ float red[16];
    int row = blockIdx.x;
    const float4* xr = (const float4*)(x + (size_t)row * Dc);
    float4 v = xr[threadIdx.x];
    float s  = v.x + v.y + v.z + v.w;
    float sq = v.x*v.x + v.y*v.y + v.z*v.z + v.w*v.w;
    #pragma unroll
    for (int off = 16; off; off >>= 1) {
        s  += __shfl_xor_sync(0xffffffffu, s,  off);
        sq += __shfl_xor_sync(0xffffffffu, sq, off);
    }
    int warp = threadIdx.x >> 5, lane = threadIdx.x & 31;
    if (lane == 0) { red[warp] = s; red[8 + warp] = sq; }
    __syncthreads();
    float ts = 0.f, tsq = 0.f;
    #pragma unroll
    for (int i = 0; i < 8; i++) { ts += red[i]; tsq += red[8 + i]; }
    float mean = ts * (1.0f / Dc);
    float var  = tsq * (1.0f / Dc) - mean * mean;
    float inv  = rsqrtf(var + 1e-5f);
    float4 g4 = ((const float4*)gamma)[threadIdx.x];
    float4 b4 = ((const float4*)beta )[threadIdx.x];
    float4 o;
    o.x = (v.x - mean) * inv * g4.x + b4.x;
    o.y = (v.y - mean) * inv * g4.y + b4.y;
    o.z = (v.z - mean) * inv * g4.z + b4.z;
    o.w = (v.w - mean) * inv * g4.w + b4.w;
    ((float4*)(out + (size_t)row * Dc))[threadIdx.x] = o;
}

// ---------------------------------------------------------------------------
// tf32 helpers
// ---------------------------------------------------------------------------
__device__ __forceinline__ uint32_t f2tf32(float f) {
    uint32_t u;
    asm("cvt.rna.tf32.f32 %0, %1;" : "=r"(u) : "f"(f));
    return u;
}

__device__ __forceinline__ void mma_tf32(float (&d)[4],
                                         const uint32_t (&a)[4],
                                         const uint32_t (&b)[2]) {
    asm volatile(
        "mma.sync.aligned.m16n8k8.row.col.f32.tf32.tf32.f32 "
        "{%0,%1,%2,%3}, {%4,%5,%6,%7}, {%8,%9}, {%0,%1,%2,%3};\n"
        : "+f"(d[0]), "+f"(d[1]), "+f"(d[2]), "+f"(d[3])
        : "r"(a[0]), "r"(a[1]), "r"(a[2]), "r"(a[3]), "r"(b[0]), "r"(b[1]));
}

// ---------------------------------------------------------------------------
// tf32 GEMM: 128x128 block, BK=16, 256 threads = 8 warps (4 M x 2 N),
// double-buffered smem, register prefetch, ONE syncthreads per k-tile.
// ---------------------------------------------------------------------------
#define ASTR 20
#define BSTR 136

template<int BMODE, int EPI>
__global__ __launch_bounds__(256) void gemm_tf32(
    const float* __restrict__ A, const float* __restrict__ B, float* __restrict__ C,
    int M, int N, int K,
    const float* __restrict__ bias, const float* __restrict__ resid)
{
    __shared__ uint32_t As[2][128 * ASTR];
    __shared__ uint32_t Bs[2][16 * BSTR];

    int m0 = blockIdx.y * 128, n0 = blockIdx.x * 128;
    int t = threadIdx.x;
    int w = t >> 5, lane = t & 31;
    int wm = w >> 1, wn = w & 1;
    int gid = lane >> 2, tid = lane & 3;

    float acc[2][8][4];
    #pragma unroll
    for (int mf = 0; mf < 2; mf++)
        #pragma unroll
        for (int nf = 0; nf < 8; nf++)
            #pragma unroll
            for (int c = 0; c < 4; c++) acc[mf][nf][c] = 0.f;

    int af0 = t, af1 = t + 256;
    int bf0 = t, bf1 = t + 256;

    float4 pa0, pa1, pb0, pb1;

    auto loadA = [&](int f, int k0) -> float4 {
        int row = f >> 2, kq = (f & 3) * 4;
        return *(const float4*)(A + (size_t)(m0 + row) * K + k0 + kq);
    };
    auto loadB = [&](int f, int k0) -> float4 {
        int k = f >> 5, nq = (f & 31) * 4;
        if (BMODE == 0)
            return *(const float4*)(B + (size_t)(k0 + k) * N + n0 + nq);
        int n = n0 + nq;
        return *(const float4*)(B + (size_t)(n >> 6) * K * 64 + (size_t)(k0 + k) * 64 + (n & 63));
    };
    auto stash = [&](int buf) {
        {   int row = af0 >> 2, kq = (af0 & 3) * 4;
            uint4 u; u.x = f2tf32(pa0.x); u.y = f2tf32(pa0.y); u.z = f2tf32(pa0.z); u.w = f2tf32(pa0.w);
            *(uint4*)&As[buf][row * ASTR + kq] = u; }
        {   int row = af1 >> 2, kq = (af1 & 3) * 4;
            uint4 u; u.x = f2tf32(pa1.x); u.y = f2tf32(pa1.y); u.z = f2tf32(pa1.z); u.w = f2tf32(pa1.w);
            *(uint4*)&As[buf][row * ASTR + kq] = u; }
        {   int k = bf0 >> 5, nq = (bf0 & 31) * 4;
            uint4 u; u.x = f2tf32(pb0.x); u.y = f2tf32(pb0.y); u.z = f2tf32(pb0.z); u.w = f2tf32(pb0.w);
            *(uint4*)&Bs[buf][k * BSTR + nq] = u; }
        {   int k = bf1 >> 5, nq = (bf1 & 31) * 4;
            uint4 u; u.x = f2tf32(pb1.x); u.y = f2tf32(pb1.y); u.z = f2tf32(pb1.z); u.w = f2tf32(pb1.w);
            *(uint4*)&Bs[buf][k * BSTR + nq] = u; }
    };
    auto compute = [&](int buf) {
        #pragma unroll
        for (int ks = 0; ks < 2; ks++) {
            int kk = ks * 8;
            uint32_t afr[2][4], bfr[8][2];
            #pragma unroll
            for (int mf = 0; mf < 2; mf++) {
                int mb = wm * 32 + mf * 16 + gid;
                afr[mf][0] = As[buf][(mb    ) * ASTR + kk + tid];
                afr[mf][1] = As[buf][(mb + 8) * ASTR + kk + tid];
                afr[mf][2] = As[buf][(mb    ) * ASTR + kk + tid + 4];
                afr[mf][3] = As[buf][(mb + 8) * ASTR + kk + tid + 4];
            }
            #pragma unroll
            for (int nf = 0; nf < 8; nf++) {
                int nb = wn * 64 + nf * 8 + gid;
                bfr[nf][0] = Bs[buf][(kk + tid    ) * BSTR + nb];
                bfr[nf][1] = Bs[buf][(kk + tid + 4) * BSTR + nb];
            }
            #pragma unroll
            for (int mf = 0; mf < 2; mf++)
                #pragma unroll
                for (int nf = 0; nf < 8; nf++)
                    mma_tf32(acc[mf][nf], afr[mf], bfr[nf]);
        }
    };

    pa0 = loadA(af0, 0); pa1 = loadA(af1, 0);
    pb0 = loadB(bf0, 0); pb1 = loadB(bf1, 0);
    stash(0);
    __syncthreads();

    int cur = 0;
    for (int k0 = 16; k0 < K; k0 += 16) {
        pa0 = loadA(af0, k0); pa1 = loadA(af1, k0);
        pb0 = loadB(bf0, k0); pb1 = loadB(bf1, k0);
        compute(cur);
        stash(cur ^ 1);
        __syncthreads();
        cur ^= 1;
    }
    compute(cur);

    #pragma unroll
    for (int mf = 0; mf < 2; mf++) {
        int r0 = m0 + wm * 32 + mf * 16 + gid;
        #pragma unroll
        for (int nf = 0; nf < 8; nf++) {
            int c0 = n0 + wn * 64 + nf * 8 + 2 * tid;
            float v0 = acc[mf][nf][0], v1 = acc[mf][nf][1];
            float v2 = acc[mf][nf][2], v3 = acc[mf][nf][3];
            if (EPI == 1) {
                float b0v = bias[c0], b1v = bias[c0 + 1];
                v0 += b0v + resid[(size_t)r0 * N + c0];
                v1 += b1v + resid[(size_t)r0 * N + c0 + 1];
                v2 += b0v + resid[(size_t)(r0 + 8) * N + c0];
                v3 += b1v + resid[(size_t)(r0 + 8) * N + c0 + 1];
            }
            if (EPI == 2) {
                float b0v = bias[c0], b1v = bias[c0 + 1];
                v0 += b0v; v1 += b1v; v2 += b0v; v3 += b1v;
                v0 = 0.5f * v0 * (1.0f + erff(v0 * 0.70710678118654752f));
                v1 = 0.5f * v1 * (1.0f + erff(v1 * 0.70710678118654752f));
                v2 = 0.5f * v2 * (1.0f + erff(v2 * 0.70710678118654752f));
                v3 = 0.5f * v3 * (1.0f + erff(v3 * 0.70710678118654752f));
            }
            *(float2*)(C + (size_t)r0 * N + c0)       = make_float2(v0, v1);
            *(float2*)(C + (size_t)(r0 + 8) * N + c0) = make_float2(v2, v3);
        }
    }
}

// ---------------------------------------------------------------------------
// Flash attention with tf32 mma. Q tile 128 x 64, KV tile 64.
// 8 warps: warp w owns rows w*16..w*16+15 and ALL 64 columns -> softmax row
// reduction stays within a lane quad (shfl xor 1,2).
// smem tiles stored as tf32 (uint32), stride 68 -> conflict-free frag loads.
// ---------------------------------------------------------------------------
#define AQ 68
#define ATTN_SMEM ((128 + 64 + 64 + 128) * AQ * 4)   // 104448 bytes

__global__ __launch_bounds__(256) void attn_mma_kernel(
    const float* __restrict__ Qg, const float* __restrict__ Kg,
    const float* __restrict__ Vg, float* __restrict__ Og)
{
    extern __shared__ uint32_t smu[];
    uint32_t* sQ = smu;                    // [128][AQ]  (q rows x e)
    uint32_t* sK = sQ + 128 * AQ;          // [64][AQ]   (k rows x e)
    uint32_t* sV = sK + 64 * AQ;           // [64][AQ]   (k rows x e)
    uint32_t* sP = sV + 64 * AQ;           // [128][AQ]  (q rows x k)

    int qt = blockIdx.x, h = blockIdx.y, b = blockIdx.z;
    int t = threadIdx.x, w = t >> 5, lane = t & 31;
    int gid = lane >> 2, tid = lane & 3;
    size_t base = ((size_t)b * Sc) * Dc + h * HDc;

    // Load + convert Q tile (128 rows x 64)
    #pragma unroll
    for (int i = 0; i < 8; i++) {
        int f = t + i * 256;               // 0..2047
        int r = f >> 4, c4 = (f & 15) * 4;
        float4 v = *(const float4*)(Qg + base + (size_t)(qt * 128 + r) * Dc + c4);
        uint4 u; u.x = f2tf32(v.x); u.y = f2tf32(v.y); u.z = f2tf32(v.z); u.w = f2tf32(v.w);
        *(uint4*)&sQ[r * AQ + c4] = u;
    }

    float m0r = -INFINITY, m1r = -INFINITY, l0 = 0.f, l1 = 0.f;
    float acc[8][4];
    #pragma unroll
    for (int nf = 0; nf < 8; nf++)
        #pragma unroll
        for (int c = 0; c < 4; c++) acc[nf][c] = 0.f;

    int row0 = qt * 128 + w * 16 + gid;
    int pr0 = (w * 16 + gid) * AQ, pr1 = (w * 16 + gid + 8) * AQ;

    int nt = 2 * qt + 2;
    for (int kt = 0; kt < nt; kt++) {
        // Load + convert K,V tiles (64 x 64 each)
        #pragma unroll
        for (int i = 0; i < 4; i++) {
            int f = t + i * 256;
            int r = f >> 4, c4 = (f & 15) * 4;
            float4 kv = *(const float4*)(Kg + base + (size_t)(kt * 64 + r) * Dc + c4);
            uint4 uk; uk.x = f2tf32(kv.x); uk.y = f2tf32(kv.y); uk.z = f2tf32(kv.z); uk.w = f2tf32(kv.w);
            *(uint4*)&sK[r * AQ + c4] = uk;
            float4 vv = *(const float4*)(Vg + base + (size_t)(kt * 64 + r) * Dc + c4);
            uint4 uv; uv.x = f2tf32(vv.x); uv.y = f2tf32(vv.y); uv.z = f2tf32(vv.z); uv.w = f2tf32(vv.w);
            *(uint4*)&sV[r * AQ + c4] = uv;
        }
        __syncthreads();

        // S = Q @ K^T  (warp rows w*16..+15, cols 0..63, k-dim = e = 64)
        float s[8][4];
        #pragma unroll
        for (int nf = 0; nf < 8; nf++)
            #pragma unroll
            for (int c = 0; c < 4; c++) s[nf][c] = 0.f;
        #pragma unroll
        for (int ks = 0; ks < 8; ks++) {
            int kk = ks * 8;
            uint32_t a[4];
            a[0] = sQ[pr0 + kk + tid];
            a[1] = sQ[pr1 + kk + tid];
            a[2] = sQ[pr0 + kk + tid + 4];
            a[3] = sQ[pr1 + kk + tid + 4];
            #pragma unroll
            for (int nf = 0; nf < 8; nf++) {
                uint32_t bb[2];
                bb[0] = sK[(nf * 8 + gid) * AQ + kk + tid];
                bb[1] = sK[(nf * 8 + gid) * AQ + kk + tid + 4];
                mma_tf32(s[nf], a, bb);
            }
        }

        // scale + causal mask (only tiles straddling the diagonal)
        bool edge = (kt >= 2 * qt);
        #pragma unroll
        for (int nf = 0; nf < 8; nf++) {
            int c0 = kt * 64 + nf * 8 + 2 * tid;
            s[nf][0] *= 0.125f; s[nf][1] *= 0.125f;
            s[nf][2] *= 0.125f; s[nf][3] *= 0.125f;
            if (edge) {
                if (c0     > row0)     s[nf][0] = -1e10f;
                if (c0 + 1 > row0)     s[nf][1] = -1e10f;
                if (c0     > row0 + 8) s[nf][2] = -1e10f;
                if (c0 + 1 > row0 + 8) s[nf][3] = -1e10f;
            }
        }

        // online softmax (row reductions within lane quad)
        float mx0 = -INFINITY, mx1 = -INFINITY;
        #pragma unroll
        for (int nf = 0; nf < 8; nf++) {
            mx0 = fmaxf(mx0, fmaxf(s[nf][0], s[nf][1]));
            mx1 = fmaxf(mx1, fmaxf(s[nf][2], s[nf][3]));
        }
        mx0 = fmaxf(mx0, __shfl_xor_sync(0xffffffffu, mx0, 1));
        mx0 = fmaxf(mx0, __shfl_xor_sync(0xffffffffu, mx0, 2));
        mx1 = fmaxf(mx1, __shfl_xor_sync(0xffffffffu, mx1, 1));
        mx1 = fmaxf(mx1, __shfl_xor_sync(0xffffffffu, mx1, 2));
        float mn0 = fmaxf(m0r, mx0), mn1 = fmaxf(m1r, mx1);
        float corr0 = __expf(m0r - mn0), corr1 = __expf(m1r - mn1);
        float sum0 = 0.f, sum1 = 0.f;
        #pragma unroll
        for (int nf = 0; nf < 8; nf++) {
            s[nf][0] = __expf(s[nf][0] - mn0); sum0 += s[nf][0];
            s[nf][1] = __expf(s[nf][1] - mn0); sum0 += s[nf][1];
            s[nf][2] = __expf(s[nf][2] - mn1); sum1 += s[nf][2];
            s[nf][3] = __expf(s[nf][3] - mn1); sum1 += s[nf][3];
        }
        sum0 += __shfl_xor_sync(0xffffffffu, sum0, 1);
        sum0 += __shfl_xor_sync(0xffffffffu, sum0, 2);
        sum1 += __shfl_xor_sync(0xffffffffu, sum1, 1);
        sum1 += __shfl_xor_sync(0xffffffffu, sum1, 2);
        l0 = l0 * corr0 + sum0;  l1 = l1 * corr1 + sum1;
        m0r = mn0;  m1r = mn1;
        #pragma unroll
        for (int nf = 0; nf < 8; nf++) {
            acc[nf][0] *= corr0; acc[nf][1] *= corr0;
            acc[nf][2] *= corr1; acc[nf][3] *= corr1;
        }

        // store P (warp-private rows -> only __syncwarp needed)
        #pragma unroll
        for (int nf = 0; nf < 8; nf++) {
            int c = nf * 8 + 2 * tid;
            sP[pr0 + c]     = f2tf32(s[nf][0]);
            sP[pr0 + c + 1] = f2tf32(s[nf][1]);
            sP[pr1 + c]     = f2tf32(s[nf][2]);
            sP[pr1 + c + 1] = f2tf32(s[nf][3]);
        }
        __syncwarp();

        // acc += P @ V   (k-dim = 64 kv rows, N = 64 e-cols)
        #pragma unroll
        for (int ks = 0; ks < 8; ks++) {
            int kk = ks * 8;
            uint32_t a[4];
            a[0] = sP[pr0 + kk + tid];
            a[1] = sP[pr1 + kk + tid];
            a[2] = sP[pr0 + kk + tid + 4];
            a[3] = sP[pr1 + kk + tid + 4];
            #pragma unroll
            for (int nf = 0; nf < 8; nf++) {
                uint32_t bb[2];
                bb[0] = sV[(kk + tid    ) * AQ + nf * 8 + gid];
                bb[1] = sV[(kk + tid + 4) * AQ + nf * 8 + gid];
                mma_tf32(acc[nf], a, bb);
            }
        }
        __syncthreads();   // before next tile overwrites sK/sV
    }

    // epilogue: O = acc / l
    float inv0 = 1.0f / l0, inv1 = 1.0f / l1;
    #pragma unroll
    for (int nf = 0; nf < 8; nf++) {
        int c = nf * 8 + 2 * tid;
        *(float2*)(Og + base + (size_t)(row0) * Dc + c) =
            make_float2(acc[nf][0] * inv0, acc[nf][1] * inv0);
        *(float2*)(Og + base + (size_t)(row0 + 8) * Dc + c) =
            make_float2(acc[nf][2] * inv1, acc[nf][3] * inv1);
    }
}

// ---------------------------------------------------------------------------
extern "C" void kernel_launch(void* const* d_in, const int* in_sizes, int n_in,
                              void* d_out, int out_size)
{
    const float* x   = (const float*)d_in[0];
    const float* Wq  = (const float*)d_in[1];
    const float* Wk  = (const float*)d_in[2];
    const float* Wv  = (const float*)d_in[3];
    const float* Wo  = (const float*)d_in[4];
    const float* bo  = (const float*)d_in[5];
    const float* g1  = (const float*)d_in[6];
    const float* b1  = (const float*)d_in[7];
    const float* g2  = (const float*)d_in[8];
    const float* b2  = (const float*)d_in[9];
    const float* W1  = (const float*)d_in[10];
    const float* bf1 = (const float*)d_in[11];
    const float* W2  = (const float*)d_in[12];
    const float* bf2 = (const float*)d_in[13];
    float* out = (float*)d_out;

    float *h, *q, *k, *v, *ctx, *cache, *h2, *ff;
    cudaGetSymbolAddress((void**)&h,     g_h);
    cudaGetSymbolAddress((void**)&q,     g_q);
    cudaGetSymbolAddress((void**)&k,     g_k);
    cudaGetSymbolAddress((void**)&v,     g_v);
    cudaGetSymbolAddress((void**)&ctx,   g_ctx);
    cudaGetSymbolAddress((void**)&cache, g_cache);
    cudaGetSymbolAddress((void**)&h2,    g_h2);
    cudaGetSymbolAddress((void**)&ff,    g_ff);

    // 1. LN1
    layernorm_kernel<<<ROWS, 256>>>(x, g1, b1, h);

    // 2. Q/K/V projections
    dim3 gqkv(Dc / 128, ROWS / 128);   // (8, 32)
    gemm_tf32<1, 0><<<gqkv, 256>>>(h, Wq, q, ROWS, Dc, Dc, nullptr, nullptr);
    gemm_tf32<1, 0><<<gqkv, 256>>>(h, Wk, k, ROWS, Dc, Dc, nullptr, nullptr);
    gemm_tf32<1, 0><<<gqkv, 256>>>(h, Wv, v, ROWS, Dc, Dc, nullptr, nullptr);

    // 3. Causal attention (tf32 mma)
    cudaFuncSetAttribute(attn_mma_kernel, cudaFuncAttributeMaxDynamicSharedMemorySize, ATTN_SMEM);
    attn_mma_kernel<<<dim3(Sc / 128, Hc, Bc), 256, ATTN_SMEM>>>(q, k, v, ctx);

    // 4. Output projection + bias + residual(x) -> cache
    gemm_tf32<0, 1><<<gqkv, 256>>>(ctx, Wo, cache, ROWS, Dc, Dc, bo, x);

    // 5. LN2
    layernorm_kernel<<<ROWS, 256>>>(cache, g2, b2, h2);

    // 6. FF1 + bias + exact GELU
    dim3 gff1(FFc / 128, ROWS / 128);  // (32, 32)
    gemm_tf32<0, 2><<<gff1, 256>>>(h2, W1, ff, ROWS, FFc, Dc, bf1, nullptr);

    // 7. FF2 + bias + residual(cache) -> out
    gemm_tf32<0, 1><<<gqkv, 256>>>(ff, W2, out, ROWS, Dc, FFc, bf2, cache);
}